// round 2
// baseline (speedup 1.0000x reference)
#include <cuda_runtime.h>

#define NN 50000
#define FF 16
#define TH 10
#define TOUT 10
#define EE 800000
#define HH 64
#define NSTEPS 40
#define NF (NN*FF)

// ---------------- scratch (static device globals; no allocs) ----------------
__device__ int    g_cnt[NN];
__device__ int    g_rowptr[NN + 1];
__device__ int    g_cursor[NN];
__device__ int    g_srcs[EE];
__device__ float4 g_eas[EE];
__device__ float  g_P[NN * 192];      // per-node projections: u(64) | v(64) | w(64)
__device__ float  g_augp[NN * HH];    // aug @ W1n_aug + b1n
__device__ float  g_x[NF];            // current state
__device__ float  g_k[6][NF];         // RK stage derivatives
__device__ float  g_ys[TOUT][NF];     // interval-end states
__device__ float  g_M[HH * HH];       // W2m @ W1n_agg
__device__ float  g_c[HH];            // b2m @ W1n_agg

// Dormand-Prince coefficients (match reference fp32 exactly)
__constant__ float c_A[6][5] = {
    {0.f, 0.f, 0.f, 0.f, 0.f},
    {0.2f, 0.f, 0.f, 0.f, 0.f},
    {3.f/40.f, 9.f/40.f, 0.f, 0.f, 0.f},
    {44.f/45.f, -56.f/15.f, 32.f/9.f, 0.f, 0.f},
    {19372.f/6561.f, -25360.f/2187.f, 64448.f/6561.f, -212.f/729.f, 0.f},
    {9017.f/3168.f, -355.f/33.f, 46732.f/5247.f, 49.f/176.f, -5103.f/18656.f}
};
__constant__ float c_C[6] = {0.f, 0.2f, 0.3f, 0.8f, 8.f/9.f, 1.f};
__constant__ float c_B[6] = {35.f/384.f, 0.f, 500.f/1113.f, 125.f/192.f, -2187.f/6784.f, 11.f/84.f};

__device__ __forceinline__ float tanh_fast(float x) {
    float ax = fabsf(x);
    float e  = __expf(ax + ax);                 // MUFU.EX2 path
    float y  = 1.f - __fdividef(2.f, e + 1.f);  // MUFU.RCP path; e=inf -> y=1
    return copysignf(y, x);
}

// ---------------- precompute kernels ----------------
__global__ void k_zero() {
    int i = blockIdx.x * blockDim.x + threadIdx.x;
    if (i < NN) g_cnt[i] = 0;
}

__global__ void k_hist(const int* __restrict__ eidx) {
    int e = blockIdx.x * blockDim.x + threadIdx.x;
    if (e < EE) atomicAdd(&g_cnt[eidx[EE + e]], 1);
}

__global__ void k_scan() {
    __shared__ int sh[1024];
    __shared__ int carry_s;
    int t = threadIdx.x;
    if (t == 0) carry_s = 0;
    __syncthreads();
    for (int base = 0; base < NN; base += 1024) {
        int v = (base + t < NN) ? g_cnt[base + t] : 0;
        int x = v;
        for (int off = 1; off < 1024; off <<= 1) {
            sh[t] = x; __syncthreads();
            if (t >= off) x += sh[t - off];
            __syncthreads();
        }
        int cprev = carry_s;
        int excl  = cprev + x - v;
        if (base + t < NN) { g_rowptr[base + t] = excl; g_cursor[base + t] = excl; }
        __syncthreads();
        if (t == 1023) carry_s = cprev + x;
        __syncthreads();
    }
    if (t == 0) g_rowptr[NN] = carry_s;
}

__global__ void k_scatter(const int* __restrict__ eidx, const float* __restrict__ eattr) {
    int e = blockIdx.x * blockDim.x + threadIdx.x;
    if (e >= EE) return;
    int src = eidx[e];
    int dst = eidx[EE + e];
    int pos = atomicAdd(&g_cursor[dst], 1);
    g_srcs[pos] = src;
    g_eas[pos]  = reinterpret_cast<const float4*>(eattr)[e];
}

__global__ void k_init_x(const float* __restrict__ x_hist) {
    int i = blockIdx.x * blockDim.x + threadIdx.x;
    if (i < NF) g_x[i] = x_hist[(TH - 1) * NF + i];
}

// M = W2m(64x16) @ W1n_agg(16x64);  c = b2m(16) @ W1n_agg
__global__ void k_M(const float* __restrict__ W2m, const float* __restrict__ W1n,
                    const float* __restrict__ b2m) {
    int tid = blockIdx.x * blockDim.x + threadIdx.x;
    if (tid < HH * HH) {
        int j = tid >> 6, i = tid & 63;
        float s = 0.f;
        #pragma unroll
        for (int k = 0; k < 16; k++) s += W2m[j * 16 + k] * W1n[(16 + k) * 64 + i];
        g_M[tid] = s;
    }
    if (tid < HH) {
        float s = 0.f;
        #pragma unroll
        for (int k = 0; k < 16; k++) s += b2m[k] * W1n[(16 + k) * 64 + tid];
        g_c[tid] = s;
    }
}

// aug features (dx_flat 144, mean 16, var 16) projected: aug @ W1n[32:208] + b1n
__global__ void k_aug(const float* __restrict__ xh, const float* __restrict__ xm,
                      const float* __restrict__ W1n, const float* __restrict__ b1n) {
    __shared__ float aug_s[8][176];
    int tid = threadIdx.x, lane = tid & 31, w = tid >> 5;
    int n = blockIdx.x * 8 + w;
    if (n >= NN) return;
    if (lane < 16) {
        int f = lane;
        float xv[TH], mv[TH];
        float sx = 0.f, sm = 0.f;
        #pragma unroll
        for (int t = 0; t < TH; t++) {
            xv[t] = xh[t * NF + n * FF + f];
            mv[t] = xm[t * NN + n];
            sx += xv[t] * mv[t];
            sm += mv[t];
        }
        float cnt  = fmaxf(sm, 1.f);
        float mean = sx / cnt;
        float var = 0.f;
        #pragma unroll
        for (int t = 0; t < TH; t++) {
            float d = xv[t] - mean;
            var += d * d * mv[t];
        }
        var /= cnt;
        #pragma unroll
        for (int t = 0; t < TH - 1; t++)
            aug_s[w][t * 16 + f] = (xv[t + 1] - xv[t]) * mv[t + 1] * mv[t];
        aug_s[w][144 + f] = mean;
        aug_s[w][160 + f] = var;
    }
    __syncwarp();
    int i0 = 2 * lane;
    float acc0 = b1n[i0], acc1 = b1n[i0 + 1];
    for (int a = 0; a < 176; a++) {
        float av = aug_s[w][a];
        float2 wv = *reinterpret_cast<const float2*>(&W1n[(32 + a) * 64 + i0]);
        acc0 += av * wv.x;
        acc1 += av * wv.y;
    }
    g_augp[n * HH + i0]     = acc0;
    g_augp[n * HH + i0 + 1] = acc1;
}

// ---------------- per-stage kernels ----------------
// xi = x + dt*sum(A[stage][j]*k_j);  P[n] = xi @ [W1a | W1b(+b1m) | W1n_x]  (16x192)
__global__ void __launch_bounds__(256)
k_proj(const float* __restrict__ t_arr, const float* __restrict__ W1m,
       const float* __restrict__ W1n, const float* __restrict__ b1m,
       int stage, int step) {
    __shared__ float xi_s[256 * 16];
    int tid = threadIdx.x, lane = tid & 31, w = tid >> 5;
    int nb = blockIdx.x * 256;
    int iv = step >> 2;
    float dt_int = (t_arr[iv + 1] - t_arr[iv]) * 0.25f;

    // weights for my 6 columns -> registers
    float wreg[96];
    float biasr[6];
    #pragma unroll
    for (int r = 0; r < 6; r++) {
        int c = lane + 32 * r;
        const float* base;
        int coff;
        if (c < 64)       { base = W1m;           coff = c; }
        else if (c < 128) { base = W1m + 16 * 64; coff = c - 64; }
        else              { base = W1n;           coff = c - 128; }
        #pragma unroll
        for (int f = 0; f < 16; f++) wreg[r * 16 + f] = base[f * 64 + coff];
        biasr[r] = (c >= 64 && c < 128) ? b1m[c - 64] : 0.f;
    }

    int nmax = NN - nb; if (nmax > 256) nmax = 256;
    for (int it = 0; it < 16; it++) {
        int idx = it * 256 + tid;
        float val = 0.f;
        if ((idx >> 4) < nmax) {
            int g = nb * 16 + idx;
            float s = 0.f;
            #pragma unroll
            for (int j = 0; j < 5; j++)
                if (j < stage) s += c_A[stage][j] * g_k[j][g];
            val = g_x[g] + dt_int * s;
        }
        xi_s[idx] = val;
    }
    __syncthreads();

    for (int nn = 0; nn < 32; nn++) {
        int nl = w * 32 + nn;
        if (nl >= nmax) break;
        float xv[16];
        #pragma unroll
        for (int f = 0; f < 16; f++) xv[f] = xi_s[nl * 16 + f];
        #pragma unroll
        for (int r = 0; r < 6; r++) {
            float acc = biasr[r];
            #pragma unroll
            for (int f = 0; f < 16; f++) acc += xv[f] * wreg[r * 16 + f];
            g_P[(nb + nl) * 192 + lane + 32 * r] = acc;
        }
    }
}

// warp per node: aggregate in-edges' tanh(u_src + v_n + ea@W1c), then node MLP -> k[stage]
__global__ void __launch_bounds__(256)
k_node(const float* __restrict__ t_arr, const float* __restrict__ W1m,
       const float* __restrict__ W1n, const float* __restrict__ W2n,
       const float* __restrict__ b2n, int stage, int step) {
    __shared__ float W1c_s[4][64];
    __shared__ float M_s[HH * HH];
    __shared__ float wt_s[64], c_s[64];
    __shared__ float W2n_s[64 * 16];
    __shared__ float b2n_s[16];
    __shared__ float hbuf[8][64];

    int tid = threadIdx.x, lane = tid & 31, w = tid >> 5;
    for (int i = tid; i < 256; i += 256)  W1c_s[i >> 6][i & 63] = W1m[(32 + (i >> 6)) * 64 + (i & 63)];
    for (int i = tid; i < HH * HH; i += 256) M_s[i] = g_M[i];
    for (int i = tid; i < 64; i += 256) { wt_s[i] = W1n[208 * 64 + i]; c_s[i] = g_c[i]; }
    for (int i = tid; i < 1024; i += 256) W2n_s[i] = W2n[i];
    if (tid < 16) b2n_s[tid] = b2n[tid];
    __syncthreads();

    int iv = step >> 2;
    float dt_int = (t_arr[iv + 1] - t_arr[iv]) * 0.25f;
    float ti = t_arr[iv] + (float)(step & 3) * dt_int + c_C[stage] * dt_int;

    float2 wc0 = {W1c_s[0][2 * lane], W1c_s[0][2 * lane + 1]};
    float2 wc1 = {W1c_s[1][2 * lane], W1c_s[1][2 * lane + 1]};
    float2 wc2 = {W1c_s[2][2 * lane], W1c_s[2][2 * lane + 1]};
    float2 wc3 = {W1c_s[3][2 * lane], W1c_s[3][2 * lane + 1]};

    for (int rep = 0; rep < 8; rep++) {
        int n = blockIdx.x * 64 + rep * 8 + w;
        if (n >= NN) continue;   // uniform per warp
        int rs = g_rowptr[n], re = g_rowptr[n + 1];
        float2 vv = *reinterpret_cast<const float2*>(&g_P[n * 192 + 64 + 2 * lane]);
        float hs0 = 0.f, hs1 = 0.f;

        // software-pipelined edge loop (prefetch depth 1)
        int src0 = 0; float4 ea0 = {0,0,0,0}; float2 uu0 = {0,0};
        if (rs < re) {
            src0 = g_srcs[rs];
            ea0  = g_eas[rs];
            uu0  = *reinterpret_cast<const float2*>(&g_P[src0 * 192 + 2 * lane]);
        }
        for (int e = rs; e < re; e++) {
            int src1 = 0; float4 ea1 = {0,0,0,0}; float2 uu1 = {0,0};
            if (e + 1 < re) {
                src1 = g_srcs[e + 1];
                ea1  = g_eas[e + 1];
                uu1  = *reinterpret_cast<const float2*>(&g_P[src1 * 192 + 2 * lane]);
            }
            float p0 = uu0.x + vv.x + ea0.x * wc0.x + ea0.y * wc1.x + ea0.z * wc2.x + ea0.w * wc3.x;
            float p1 = uu0.y + vv.y + ea0.x * wc0.y + ea0.y * wc1.y + ea0.z * wc2.y + ea0.w * wc3.y;
            hs0 += tanh_fast(p0);
            hs1 += tanh_fast(p1);
            src0 = src1; ea0 = ea1; uu0 = uu1;
        }

        hbuf[w][2 * lane] = hs0; hbuf[w][2 * lane + 1] = hs1;
        __syncwarp();

        float deg = (float)(re - rs);
        float2 ww = *reinterpret_cast<const float2*>(&g_P[n * 192 + 128 + 2 * lane]);
        float2 ap = *reinterpret_cast<const float2*>(&g_augp[n * HH + 2 * lane]);
        float a0 = ww.x + deg * c_s[2 * lane]     + ti * wt_s[2 * lane]     + ap.x;
        float a1 = ww.y + deg * c_s[2 * lane + 1] + ti * wt_s[2 * lane + 1] + ap.y;
        for (int j = 0; j < 64; j++) {
            float hj = hbuf[w][j];
            float2 mv = *reinterpret_cast<const float2*>(&M_s[j * 64 + 2 * lane]);
            a0 += hj * mv.x;
            a1 += hj * mv.y;
        }
        float h20 = tanh_fast(a0), h21 = tanh_fast(a1);
        __syncwarp();
        hbuf[w][2 * lane] = h20; hbuf[w][2 * lane + 1] = h21;
        __syncwarp();
        if (lane < 16) {
            float acc = b2n_s[lane];
            for (int j = 0; j < 64; j++) acc += hbuf[w][j] * W2n_s[j * 16 + lane];
            g_k[stage][n * 16 + lane] = acc;
        }
        __syncwarp();
    }
}

__global__ void k_combine(const float* __restrict__ t_arr, int step) {
    int i = blockIdx.x * blockDim.x + threadIdx.x;
    if (i >= NF) return;
    int iv = step >> 2;
    float dt_int = (t_arr[iv + 1] - t_arr[iv]) * 0.25f;
    float s = c_B[0] * g_k[0][i] + c_B[2] * g_k[2][i] + c_B[3] * g_k[3][i]
            + c_B[4] * g_k[4][i] + c_B[5] * g_k[5][i];
    float xn = g_x[i] + dt_int * s;
    g_x[i] = xn;
    if ((step & 3) == 3) g_ys[iv][i] = xn;
}

__global__ void k_out(const int* __restrict__ midx, float* __restrict__ out) {
    int idx = blockIdx.x * blockDim.x + threadIdx.x;
    if (idx >= TOUT * NF) return;
    int r = idx / NF;
    out[idx] = g_ys[midx[r]][idx - r * NF];
}

// ---------------- launch ----------------
extern "C" void kernel_launch(void* const* d_in, const int* in_sizes, int n_in,
                              void* d_out, int out_size) {
    const float* x_hist = (const float*)d_in[0];
    const float* x_mask = (const float*)d_in[1];
    const int*   eidx   = (const int*)  d_in[2];
    const float* eattr  = (const float*)d_in[3];
    const float* t_arr  = (const float*)d_in[4];
    const int*   midx   = (const int*)  d_in[5];
    const float* W1m = (const float*)d_in[6];
    const float* b1m = (const float*)d_in[7];
    const float* W2m = (const float*)d_in[8];
    const float* b2m = (const float*)d_in[9];
    const float* W1n = (const float*)d_in[10];
    const float* b1n = (const float*)d_in[11];
    const float* W2n = (const float*)d_in[12];
    const float* b2n = (const float*)d_in[13];
    float* out = (float*)d_out;

    k_zero   <<<(NN + 255) / 256, 256>>>();
    k_hist   <<<(EE + 255) / 256, 256>>>(eidx);
    k_scan   <<<1, 1024>>>();
    k_scatter<<<(EE + 255) / 256, 256>>>(eidx, eattr);
    k_init_x <<<(NF + 255) / 256, 256>>>(x_hist);
    k_M      <<<(HH * HH + 255) / 256, 256>>>(W2m, W1n, b2m);
    k_aug    <<<(NN + 7) / 8, 256>>>(x_hist, x_mask, W1n, b1n);

    for (int step = 0; step < NSTEPS; step++) {
        for (int stage = 0; stage < 6; stage++) {
            k_proj<<<(NN + 255) / 256, 256>>>(t_arr, W1m, W1n, b1m, stage, step);
            k_node<<<(NN + 63) / 64, 256>>>(t_arr, W1m, W1n, W2n, b2n, stage, step);
        }
        k_combine<<<(NF + 255) / 256, 256>>>(t_arr, step);
    }
    k_out<<<(TOUT * NF + 255) / 256, 256>>>(midx, out);
}